// round 3
// baseline (speedup 1.0000x reference)
#include <cuda_runtime.h>

#define ALPHA_F 0.1f
#define BETA_F  1.1f
#define NCLS    16
#define DIMS    512
#define EPS_F   1e-8f
#define FULLMASK 0xffffffffu

// ---------------- device scratch (no allocations allowed) ----------------
__device__ float  g_sums[NCLS * DIMS];
__device__ float  g_cnt[NCLS];
__device__ float  g_chat[NCLS * DIMS];
__device__ float  g_W[NCLS * NCLS];
__device__ float  g_deg[NCLS];
__device__ float  g_denom;
__device__ float  g_numpairs;
__device__ double g_acc;

// ---------------- helpers ----------------
__device__ __forceinline__ unsigned long long ffma2(unsigned long long a,
                                                    unsigned long long b,
                                                    unsigned long long c) {
    unsigned long long d;
    asm("fma.rn.f32x2 %0, %1, %2, %3;" : "=l"(d) : "l"(a), "l"(b), "l"(c));
    return d;
}
__device__ __forceinline__ float ull_hsum(unsigned long long v) {
    return __uint_as_float((unsigned)(v & 0xffffffffu)) +
           __uint_as_float((unsigned)(v >> 32));
}

// ---------------- kernel 0: zero scratch ----------------
__global__ void zero_kernel() {
    int t = threadIdx.x;
    for (int i = t; i < NCLS * DIMS; i += blockDim.x) g_sums[i] = 0.f;
    if (t < NCLS) g_cnt[t] = 0.f;
    if (t == 0) g_acc = 0.0;
}

// ---------------- kernel 1: class sums + counts ----------------
// block = 128 threads; thread t owns dims [4t, 4t+4). SMEM accumulation,
// no atomics in the loop; one atomic flush per block at the end.
__global__ void __launch_bounds__(128) pass1_kernel(const float* __restrict__ x,
                                                    const int* __restrict__ labels,
                                                    int N) {
    __shared__ __align__(16) float s_sum[NCLS * DIMS];
    __shared__ float s_cnt[NCLS];
    int t = threadIdx.x;
    for (int i = t; i < NCLS * DIMS; i += 128) s_sum[i] = 0.f;
    if (t < NCLS) s_cnt[t] = 0.f;
    __syncthreads();

    int chunk = (N + gridDim.x - 1) / gridDim.x;
    int start = blockIdx.x * chunk;
    int end   = min(start + chunk, N);

    const float4* x4 = (const float4*)x;
    float4* s4 = (float4*)s_sum;

    for (int n = start; n < end; n++) {
        int lab = __ldg(&labels[n]);                       // broadcast
        float4 v = __ldg(&x4[(size_t)n * 128 + t]);        // coalesced 2KB/row
        float4* sp = s4 + lab * 128 + t;                   // thread-private slice
        float4 s = *sp;
        s.x += v.x; s.y += v.y; s.z += v.z; s.w += v.w;
        *sp = s;
        if (t == 0) s_cnt[lab] += 1.f;
    }
    __syncthreads();
    for (int i = t; i < NCLS * DIMS; i += 128) atomicAdd(&g_sums[i], s_sum[i]);
    if (t < NCLS) atomicAdd(&g_cnt[t], s_cnt[t]);
}

// ---------------- kernel 2: centroids, pair mask, deg, W, denom ----------------
__global__ void __launch_bounds__(512) centroid_kernel() {
    __shared__ __align__(16) float s_chat[NCLS * DIMS];
    __shared__ float s_pm[NCLS * NCLS];
    __shared__ float s_cnt[NCLS];
    __shared__ float s_dg[NCLS];
    int tid = threadIdx.x;
    int warp = tid >> 5, lane = tid & 31;

    if (warp < NCLS) {   // one warp per class: centroid + normalize
        float cntc = g_cnt[warp];
        float cs = 1.f / fmaxf(cntc, 1.f);
        float cent[16];
        float ss = 0.f;
#pragma unroll
        for (int j = 0; j < 16; j++) {
            float v = g_sums[warp * DIMS + lane + 32 * j] * cs;
            cent[j] = v;
            ss += v * v;
        }
#pragma unroll
        for (int o = 16; o > 0; o >>= 1) ss += __shfl_xor_sync(FULLMASK, ss, o);
        float s2 = 1.f / fmaxf(sqrtf(ss), EPS_F);
#pragma unroll
        for (int j = 0; j < 16; j++)
            s_chat[warp * DIMS + lane + 32 * j] = cent[j] * s2;
    }
    if (tid < NCLS) s_cnt[tid] = g_cnt[tid];
    __syncthreads();

    for (int i = tid; i < NCLS * DIMS; i += 512) g_chat[i] = s_chat[i];

    if (tid < 256) {     // 16x16 pairwise cosine distance
        int i = tid >> 4, j = tid & 15;
        float dot = 0.f;
        for (int dd = 0; dd < DIMS; dd++) {
            int d = (dd + j) & (DIMS - 1);   // rotate to avoid bank conflicts
            dot += s_chat[i * DIMS + d] * s_chat[j * DIMS + d];
        }
        float pd = 1.f - dot;
        float pm = (i < j && pd <= BETA_F && s_cnt[i] > 0.f && s_cnt[j] > 0.f)
                       ? 1.f : 0.f;
        s_pm[tid] = pm;
    }
    __syncthreads();

    if (tid < NCLS) {
        float dg = 0.f;
        for (int j = 0; j < 16; j++) dg += s_pm[tid * 16 + j] + s_pm[j * 16 + tid];
        g_deg[tid] = dg;
        s_dg[tid] = dg;
    }
    if (tid < 256)
        g_W[tid] = s_pm[tid] + s_pm[(tid & 15) * 16 + (tid >> 4)];
    __syncthreads();

    if (tid == 0) {
        float count = 0.f, np = 0.f;
        for (int c = 0; c < NCLS; c++) count += s_dg[c] * s_cnt[c];
        for (int k = 0; k < 256; k++) np += s_pm[k];
        g_denom = fmaxf(count, 1.f);
        g_numpairs = np;
    }
}

// ---------------- kernel 3: per-sample distances + fused loss accumulation ----------------
// block = 256 threads (8 warps). Half-warp (16 lanes) per sample; a warp
// processes 2 samples per iteration. Lane l owns dims {2l + 32k}.
__global__ void __launch_bounds__(256) pass2_kernel(const float* __restrict__ x,
                                                    const int* __restrict__ labels,
                                                    int N) {
    __shared__ __align__(16) float s_chat[NCLS * DIMS];
    __shared__ float s_W[NCLS * 17];     // stride 17 -> conflict-free lane reads
    __shared__ float s_deg[NCLS];
    __shared__ float s_part[8];

    int tid = threadIdx.x;
    for (int i = tid; i < NCLS * DIMS; i += 256) s_chat[i] = g_chat[i];
    if (tid < 256) s_W[(tid >> 4) * 17 + (tid & 15)] = g_W[tid];
    if (tid < NCLS) s_deg[tid] = g_deg[tid];
    __syncthreads();

    const unsigned long long* chat2 = (const unsigned long long*)s_chat;
    const unsigned long long* xu = (const unsigned long long*)x;

    int warp = tid >> 5, lane = tid & 31, lg = lane & 15;
    int hi = lane >> 4;
    int gw = blockIdx.x * 8 + warp;
    int npairs = (N + 1) >> 1;
    int stride = gridDim.x * 8;

    float accsum = 0.f;

    for (int p = gw; p < npairs; p += stride) {
        int n = 2 * p + hi;
        int valid = (n < N);
        int nn_ = valid ? n : 0;
        const unsigned long long* row = xu + (size_t)nn_ * 256;

        unsigned long long xv[16];
#pragma unroll
        for (int k = 0; k < 16; k++) xv[k] = __ldg(&row[lg + 16 * k]);

        unsigned long long acc[16];
        unsigned long long nrm2 = 0ull;
#pragma unroll
        for (int c = 0; c < 16; c++) acc[c] = 0ull;

#pragma unroll
        for (int k = 0; k < 16; k++) {
            unsigned long long xk = xv[k];
            nrm2 = ffma2(xk, xk, nrm2);
#pragma unroll
            for (int c = 0; c < 16; c++)
                acc[c] = ffma2(xk, chat2[c * 256 + lg + 16 * k], acc[c]);
        }

        // reduce ||x||^2 across the 16-lane group (masks <=8 keep halves apart)
        float nn = ull_hsum(nrm2);
        nn += __shfl_xor_sync(FULLMASK, nn, 8);
        nn += __shfl_xor_sync(FULLMASK, nn, 4);
        nn += __shfl_xor_sync(FULLMASK, nn, 2);
        nn += __shfl_xor_sync(FULLMASK, nn, 1);

        float mydot = 0.f;
#pragma unroll
        for (int c = 0; c < 16; c++) {
            float v = ull_hsum(acc[c]);
            v += __shfl_xor_sync(FULLMASK, v, 8);
            v += __shfl_xor_sync(FULLMASK, v, 4);
            v += __shfl_xor_sync(FULLMASK, v, 2);
            v += __shfl_xor_sync(FULLMASK, v, 1);
            if (lg == c) mydot = v;   // lane l keeps class l's dot
        }

        int lab = __ldg(&labels[nn_]);
        float inv = 1.f / fmaxf(sqrtf(nn), EPS_F);
        float cosv = mydot * inv;

        // inter: W[lg][lab] * relu(beta - (1 - cos));  intra on lane lg==lab
        float contrib = s_W[lg * 17 + lab] * fmaxf(BETA_F - 1.f + cosv, 0.f);
        if (lg == lab)
            contrib += s_deg[lab] * fmaxf((1.f - cosv) - ALPHA_F, 0.f);

        contrib += __shfl_xor_sync(FULLMASK, contrib, 1);
        contrib += __shfl_xor_sync(FULLMASK, contrib, 2);
        contrib += __shfl_xor_sync(FULLMASK, contrib, 4);
        contrib += __shfl_xor_sync(FULLMASK, contrib, 8);
        if (lg == 0 && valid) accsum += contrib;
    }

    // block reduction -> one fp64 atomic per block
    accsum += __shfl_xor_sync(FULLMASK, accsum, 16);
    accsum += __shfl_xor_sync(FULLMASK, accsum, 8);
    accsum += __shfl_xor_sync(FULLMASK, accsum, 4);
    accsum += __shfl_xor_sync(FULLMASK, accsum, 2);
    accsum += __shfl_xor_sync(FULLMASK, accsum, 1);
    if (lane == 0) s_part[warp] = accsum;
    __syncthreads();
    if (tid == 0) {
        float tot = 0.f;
        for (int w = 0; w < 8; w++) tot += s_part[w];
        atomicAdd(&g_acc, (double)tot);
    }
}

// ---------------- kernel 4: finalize ----------------
__global__ void final_kernel(float* out) {
    out[0] = (g_numpairs > 0.f) ? (float)(g_acc / (double)g_denom) : 0.f;
}

// ---------------- launch ----------------
extern "C" void kernel_launch(void* const* d_in, const int* in_sizes, int n_in,
                              void* d_out, int out_size) {
    int ei = 0, li = 1;
    if (n_in >= 2 && in_sizes[0] < in_sizes[1]) { ei = 1; li = 0; }  // labels = smaller
    const float* x = (const float*)d_in[ei];
    const int* labels = (const int*)d_in[li];
    int N = in_sizes[li];

    zero_kernel<<<1, 256>>>();
    pass1_kernel<<<296, 128>>>(x, labels, N);
    centroid_kernel<<<1, 512>>>();
    pass2_kernel<<<296, 256>>>(x, labels, N);
    final_kernel<<<1, 1>>>((float*)d_out);
}

// round 6
// speedup vs baseline: 1.0508x; 1.0508x over previous
#include <cuda_runtime.h>

#define ALPHA_F 0.1f
#define BETA_F  1.1f
#define NCLS    16
#define DIMS    512
#define EPS_F   1e-8f
#define FULLMASK 0xffffffffu

typedef unsigned long long ull;

// ---------------- device scratch ----------------
__device__ __align__(16) float g_sums[NCLS * DIMS];
__device__ float  g_cnt[NCLS];
__device__ __align__(16) float g_chat[NCLS * DIMS];
__device__ float  g_W[NCLS * NCLS];
__device__ float  g_deg[NCLS];
__device__ float  g_denom;
__device__ float  g_numpairs;
__device__ double g_acc;
__device__ unsigned int g_tile;

// ---------------- helpers ----------------
__device__ __forceinline__ ull ffma2(ull a, ull b, ull c) {
    ull d;
    asm("fma.rn.f32x2 %0, %1, %2, %3;" : "=l"(d) : "l"(a), "l"(b), "l"(c));
    return d;
}
__device__ __forceinline__ ull add2(ull a, ull b) {
    ull d;
    asm("add.rn.f32x2 %0, %1, %2;" : "=l"(d) : "l"(a), "l"(b));
    return d;
}
__device__ __forceinline__ float ull_hsum(ull v) {
    return __uint_as_float((unsigned)(v & 0xffffffffu)) +
           __uint_as_float((unsigned)(v >> 32));
}

// ---------------- kernel 0: zero scratch ----------------
__global__ void zero_kernel() {
    int t = threadIdx.x;
    for (int i = t; i < NCLS * DIMS; i += blockDim.x) g_sums[i] = 0.f;
    if (t < NCLS) g_cnt[t] = 0.f;
    if (t == 0) { g_acc = 0.0; g_tile = 0u; }
}

// ---------------- kernel 1a: label histogram ----------------
__global__ void __launch_bounds__(256) count_kernel(const int* __restrict__ labels, int N) {
    __shared__ int sc[NCLS];
    int t = threadIdx.x;
    if (t < NCLS) sc[t] = 0;
    __syncthreads();
    for (int i = blockIdx.x * 256 + t; i < N; i += gridDim.x * 256)
        atomicAdd(&sc[__ldg(&labels[i])], 1);
    __syncthreads();
    if (t < NCLS) atomicAdd(&g_cnt[t], (float)sc[t]);
}

// ---------------- kernel 1b: class sums (register accumulation) ----------------
// 256 threads = 2 groups x 128. Thread owns 16B granule l (dims 4l..4l+3) as
// one packed f32x2 pair per class (64 regs). lab is group-uniform -> uniform
// switch, no smem chain. Sample loop unrolled x4 with front-batched LDG.128
// for MLP (~32KB/SM in flight).
__device__ __forceinline__ void accum1(ulonglong2* acc, ulonglong2 v, int lab) {
#define CASE_(c) case c: acc[c].x = add2(acc[c].x, v.x); acc[c].y = add2(acc[c].y, v.y); break;
    switch (lab) {
        CASE_(0)  CASE_(1)  CASE_(2)  CASE_(3)
        CASE_(4)  CASE_(5)  CASE_(6)  CASE_(7)
        CASE_(8)  CASE_(9)  CASE_(10) CASE_(11)
        CASE_(12) CASE_(13) CASE_(14) default:
        acc[15].x = add2(acc[15].x, v.x); acc[15].y = add2(acc[15].y, v.y); break;
    }
#undef CASE_
}

__global__ void __launch_bounds__(256) pass1_kernel(const float* __restrict__ x,
                                                    const int* __restrict__ labels,
                                                    int N) {
    __shared__ ulonglong2 s_red2[NCLS * 128];
    int t = threadIdx.x;
    int g = t >> 7;            // group 0..1
    int l = t & 127;           // granule: dims [4l, 4l+4)

    ulonglong2 acc[NCLS];
#pragma unroll
    for (int c = 0; c < NCLS; c++) { acc[c].x = 0ull; acc[c].y = 0ull; }

    int chunk = (N + gridDim.x - 1) / gridDim.x;
    int start = blockIdx.x * chunk;
    int end = min(start + chunk, N);
    int span = max(end - start, 0);
    int full = span & ~7;

    const ulonglong2* x2 = (const ulonglong2*)x;

    for (int i = g; i < full; i += 8) {          // group handles offsets i, i+2, i+4, i+6
        int n = start + i;
        const ulonglong2* r = x2 + (size_t)n * 128 + l;
        ulonglong2 v0 = __ldg(r);
        ulonglong2 v1 = __ldg(r + 256);
        ulonglong2 v2 = __ldg(r + 512);
        ulonglong2 v3 = __ldg(r + 768);
        int lab0 = __ldg(&labels[n]);
        int lab1 = __ldg(&labels[n + 2]);
        int lab2 = __ldg(&labels[n + 4]);
        int lab3 = __ldg(&labels[n + 6]);
        accum1(acc, v0, lab0);
        accum1(acc, v1, lab1);
        accum1(acc, v2, lab2);
        accum1(acc, v3, lab3);
    }
    for (int i = full + g; i < span; i += 2) {   // tail, same parity split
        int n = start + i;
        ulonglong2 v = __ldg(x2 + (size_t)n * 128 + l);
        accum1(acc, v, __ldg(&labels[n]));
    }

    // merge the 2 groups through smem, then one atomic flush per element
    if (g == 0) {
#pragma unroll
        for (int c = 0; c < NCLS; c++) s_red2[c * 128 + l] = acc[c];
    }
    __syncthreads();
    if (g == 1) {
#pragma unroll
        for (int c = 0; c < NCLS; c++) {
            ulonglong2 p = s_red2[c * 128 + l];
            p.x = add2(p.x, acc[c].x);
            p.y = add2(p.y, acc[c].y);
            s_red2[c * 128 + l] = p;
        }
    }
    __syncthreads();
    const float* s_red = (const float*)s_red2;
    for (int i = t; i < NCLS * DIMS; i += 256) atomicAdd(&g_sums[i], s_red[i]);
}

// ---------------- kernel 2: centroids, pair mask, deg, W, denom ----------------
__global__ void __launch_bounds__(512) centroid_kernel() {
    __shared__ __align__(16) float s_chat[NCLS * DIMS];
    __shared__ float s_pm[NCLS * NCLS];
    __shared__ float s_cnt[NCLS];
    __shared__ float s_dg[NCLS];
    int tid = threadIdx.x;
    int warp = tid >> 5, lane = tid & 31;

    if (warp < NCLS) {
        float cntc = g_cnt[warp];
        float cs = 1.f / fmaxf(cntc, 1.f);
        float cent[16];
        float ss = 0.f;
#pragma unroll
        for (int j = 0; j < 16; j++) {
            float v = g_sums[warp * DIMS + lane + 32 * j] * cs;
            cent[j] = v;
            ss += v * v;
        }
#pragma unroll
        for (int o = 16; o > 0; o >>= 1) ss += __shfl_xor_sync(FULLMASK, ss, o);
        float s2 = 1.f / fmaxf(sqrtf(ss), EPS_F);
#pragma unroll
        for (int j = 0; j < 16; j++)
            s_chat[warp * DIMS + lane + 32 * j] = cent[j] * s2;
    }
    if (tid < NCLS) s_cnt[tid] = g_cnt[tid];
    __syncthreads();

    for (int i = tid; i < NCLS * DIMS; i += 512) g_chat[i] = s_chat[i];

    if (tid < 256) {
        int i = tid >> 4, j = tid & 15;
        float dot = 0.f;
        for (int dd = 0; dd < DIMS; dd++) {
            int d = (dd + j) & (DIMS - 1);
            dot += s_chat[i * DIMS + d] * s_chat[j * DIMS + d];
        }
        float pd = 1.f - dot;
        s_pm[tid] = (i < j && pd <= BETA_F && s_cnt[i] > 0.f && s_cnt[j] > 0.f)
                        ? 1.f : 0.f;
    }
    __syncthreads();

    if (tid < NCLS) {
        float dg = 0.f;
        for (int j = 0; j < 16; j++) dg += s_pm[tid * 16 + j] + s_pm[j * 16 + tid];
        g_deg[tid] = dg;
        s_dg[tid] = dg;
    }
    if (tid < 256)
        g_W[tid] = s_pm[tid] + s_pm[(tid & 15) * 16 + (tid >> 4)];
    __syncthreads();

    if (tid == 0) {
        float count = 0.f, np = 0.f;
        for (int c = 0; c < NCLS; c++) count += s_dg[c] * s_cnt[c];
        for (int k = 0; k < 256; k++) np += s_pm[k];
        g_denom = fmaxf(count, 1.f);
        g_numpairs = np;
    }
}

// ---------------- kernel 3: per-sample distances + fused loss ----------------
// Thread-per-sample: tile of 256 samples per CTA iteration, X staged through
// SMEM in 32-dim chunks (conflict-free pad-9 layout), centroids read as
// warp-broadcast LDS.128. Atomic tile queue for balance.
__global__ void __launch_bounds__(256) pass2_kernel(const float* __restrict__ x,
                                                    const int* __restrict__ labels,
                                                    int N, int ntiles) {
    __shared__ ulonglong2 s_chat2[NCLS * 128];   // [c][granule], 32KB, broadcast reads
    __shared__ ulonglong2 s_x2[256 * 9];         // 256 samples x 8 granules (+pad)
    __shared__ float s_W[NCLS * 17];
    __shared__ float s_deg[NCLS];
    __shared__ float s_part[8];
    __shared__ unsigned s_tile;

    int tid = threadIdx.x;
    const ulonglong2* gchat2 = (const ulonglong2*)g_chat;
    for (int i = tid; i < NCLS * 128; i += 256) s_chat2[i] = gchat2[i];
    s_W[(tid >> 4) * 17 + (tid & 15)] = g_W[tid];
    if (tid < NCLS) s_deg[tid] = g_deg[tid];
    __syncthreads();

    const ulonglong2* x2 = (const ulonglong2*)x;
    int warp = tid >> 5, lane = tid & 31;
    int s_local = tid >> 3;     // staging: sample slot 0..31
    int d4s = tid & 7;          // staging: granule 0..7
    float accsum = 0.f;

    while (true) {
        if (tid == 0) s_tile = atomicAdd(&g_tile, 1u);
        __syncthreads();
        unsigned tile = s_tile;
        if (tile >= (unsigned)ntiles) break;
        int n0 = (int)tile * 256;
        int n = n0 + tid;
        int valid = (n < N);

        ull accp[NCLS];
#pragma unroll
        for (int c = 0; c < NCLS; c++) accp[c] = 0ull;
        ull nrm = 0ull;

        for (int ch = 0; ch < 16; ch++) {
            __syncthreads();    // protect s_x2 reuse
#pragma unroll
            for (int i = 0; i < 8; i++) {
                int s = s_local + 32 * i;
                int gs = n0 + s;
                ulonglong2 v;
                if (gs < N) v = __ldg(&x2[(size_t)gs * 128 + ch * 8 + d4s]);
                else { v.x = 0ull; v.y = 0ull; }
                s_x2[s * 9 + d4s] = v;
            }
            __syncthreads();
#pragma unroll
            for (int d4i = 0; d4i < 8; d4i++) {
                ulonglong2 xv = s_x2[tid * 9 + d4i];
                nrm = ffma2(xv.x, xv.x, ffma2(xv.y, xv.y, nrm));
#pragma unroll
                for (int c = 0; c < NCLS; c++) {
                    ulonglong2 cv = s_chat2[c * 128 + ch * 8 + d4i];
                    accp[c] = ffma2(xv.x, cv.x, ffma2(xv.y, cv.y, accp[c]));
                }
            }
        }

        // epilogue: fused relu-loss, all in-thread
        float nn = ull_hsum(nrm);
        float inv = 1.f / fmaxf(sqrtf(nn), EPS_F);
        int lab = valid ? __ldg(&labels[n]) : 0;
        float dg = s_deg[lab];
        float contrib = 0.f;
#pragma unroll
        for (int c = 0; c < NCLS; c++) {
            float cosv = ull_hsum(accp[c]) * inv;
            contrib += s_W[c * 17 + lab] * fmaxf(BETA_F - 1.f + cosv, 0.f);
            if (c == lab)
                contrib += dg * fmaxf((1.f - cosv) - ALPHA_F, 0.f);
        }
        if (valid) accsum += contrib;
    }

    // block reduction -> one fp64 atomic per block
#pragma unroll
    for (int o = 16; o > 0; o >>= 1)
        accsum += __shfl_xor_sync(FULLMASK, accsum, o);
    if (lane == 0) s_part[warp] = accsum;
    __syncthreads();
    if (tid == 0) {
        float tot = 0.f;
        for (int w = 0; w < 8; w++) tot += s_part[w];
        atomicAdd(&g_acc, (double)tot);
    }
}

// ---------------- kernel 4: finalize ----------------
__global__ void final_kernel(float* out) {
    out[0] = (g_numpairs > 0.f) ? (float)(g_acc / (double)g_denom) : 0.f;
}

// ---------------- launch ----------------
extern "C" void kernel_launch(void* const* d_in, const int* in_sizes, int n_in,
                              void* d_out, int out_size) {
    int ei = 0, li = 1;
    if (n_in >= 2 && in_sizes[0] < in_sizes[1]) { ei = 1; li = 0; }
    const float* x = (const float*)d_in[ei];
    const int* labels = (const int*)d_in[li];
    int N = in_sizes[li];
    int ntiles = (N + 255) / 256;

    zero_kernel<<<1, 256>>>();
    count_kernel<<<148, 256>>>(labels, N);
    pass1_kernel<<<148, 256>>>(x, labels, N);
    centroid_kernel<<<1, 512>>>();
    pass2_kernel<<<444, 256>>>(x, labels, N, ntiles);
    final_kernel<<<1, 1>>>((float*)d_out);
}